// round 2
// baseline (speedup 1.0000x reference)
#include <cuda_runtime.h>

// Net_43490838839931: batched RK4 of ds/dt = MLP([s,u]) with 2->4->1 LeakyReLU net.
// One thread per batch element; weights in registers; u-dependent bias folded in.
// Output [B,100] written as 25 x float4 per thread (16B-aligned since 400 % 16 == 0).

#define NSTEPS 100
#define NEG_SLOPE 0.01f

__global__ __launch_bounds__(256) void rk4_kernel(
    const float* __restrict__ x, const float* __restrict__ u,
    const float* __restrict__ W1, const float* __restrict__ b1,
    const float* __restrict__ W2, const float* __restrict__ b2,
    float* __restrict__ out, int B)
{
    int b = blockIdx.x * blockDim.x + threadIdx.x;
    if (b >= B) return;

    // W1 is [2,4] row-major: row 0 multiplies s, row 1 multiplies u.
    const float w1a0 = W1[0], w1a1 = W1[1], w1a2 = W1[2], w1a3 = W1[3];
    const float w1b0 = W1[4], w1b1 = W1[5], w1b2 = W1[6], w1b3 = W1[7];
    const float uu = u[b];
    // Fold u contribution + b1 into per-thread bias c[j].
    const float c0 = fmaf(uu, w1b0, b1[0]);
    const float c1 = fmaf(uu, w1b1, b1[1]);
    const float c2 = fmaf(uu, w1b2, b1[2]);
    const float c3 = fmaf(uu, w1b3, b1[3]);
    const float w20 = W2[0], w21 = W2[1], w22 = W2[2], w23 = W2[3];
    const float bb2 = b2[0];

    auto dyn = [&](float ss) -> float {
        float h0 = fmaf(ss, w1a0, c0);
        float h1 = fmaf(ss, w1a1, c1);
        float h2 = fmaf(ss, w1a2, c2);
        float h3 = fmaf(ss, w1a3, c3);
        // LeakyReLU(h) == max(h, 0.01*h)
        h0 = fmaxf(h0, NEG_SLOPE * h0);
        h1 = fmaxf(h1, NEG_SLOPE * h1);
        h2 = fmaxf(h2, NEG_SLOPE * h2);
        h3 = fmaxf(h3, NEG_SLOPE * h3);
        float acc = bb2;
        acc = fmaf(w20, h0, acc);
        acc = fmaf(w21, h1, acc);
        acc = fmaf(w22, h2, acc);
        acc = fmaf(w23, h3, acc);
        return acc;
    };

    auto stepf = [&](float ss) -> float {
        float k1 = dyn(ss);
        float k2 = dyn(fmaf(0.5f, k1, ss));
        float k3 = dyn(fmaf(0.5f, k2, ss));
        float k4 = dyn(ss + k3);
        float sum = fmaf(2.0f, k2 + k3, k1 + k4);
        return fmaf(sum, 0.16666667f, ss);  // dt/6
    };

    float s = x[b];

    float4* out4 = reinterpret_cast<float4*>(out) + (long long)b * (NSTEPS / 4);

    // First group: t=0 is the initial state, then 3 steps.
    float4 v;
    v.x = s;
    s = stepf(s); v.y = s;
    s = stepf(s); v.z = s;
    s = stepf(s); v.w = s;
    out4[0] = v;

    // Remaining 24 groups of 4 steps each (96 steps -> total 99 steps).
    #pragma unroll 4
    for (int g = 1; g < NSTEPS / 4; ++g) {
        s = stepf(s); v.x = s;
        s = stepf(s); v.y = s;
        s = stepf(s); v.z = s;
        s = stepf(s); v.w = s;
        out4[g] = v;
    }
}

extern "C" void kernel_launch(void* const* d_in, const int* in_sizes, int n_in,
                              void* d_out, int out_size)
{
    const float* x  = (const float*)d_in[0];
    const float* u  = (const float*)d_in[1];
    const float* W1 = (const float*)d_in[2];
    const float* b1 = (const float*)d_in[3];
    const float* W2 = (const float*)d_in[4];
    const float* b2 = (const float*)d_in[5];
    float* out = (float*)d_out;
    int B = in_sizes[0];

    int threads = 256;
    int blocks = (B + threads - 1) / threads;
    rk4_kernel<<<blocks, threads>>>(x, u, W1, b1, W2, b2, out, B);
}

// round 4
// speedup vs baseline: 1.1290x; 1.1290x over previous
#include <cuda_runtime.h>

// Net_43490838839931: batched RK4 of ds/dt = MLP([s,u]) with 2->4->1 LeakyReLU net.
// R2: (a) LeakyReLU folded into output layer: sum w2*lrelu(h) = sum p*h + q*|h|
//     with p=0.505*w2, q=0.495*w2  (lrelu(h) = 0.505h + 0.495|h| for slope 0.01)
//     (b) 2 batch elements per thread via packed fma.rn.f32x2 / add.rn.f32x2.

#define NSTEPS 100

typedef unsigned long long u64;

__device__ __forceinline__ u64 pack2(float lo, float hi) {
    u64 r; asm("mov.b64 %0, {%1, %2};" : "=l"(r) : "f"(lo), "f"(hi)); return r;
}
__device__ __forceinline__ void unpack2(u64 v, float& a, float& b) {
    asm("mov.b64 {%0, %1}, %2;" : "=f"(a), "=f"(b) : "l"(v));
}
__device__ __forceinline__ u64 fma2(u64 a, u64 b, u64 c) {
    u64 d; asm("fma.rn.f32x2 %0, %1, %2, %3;" : "=l"(d) : "l"(a), "l"(b), "l"(c)); return d;
}
__device__ __forceinline__ u64 mul2(u64 a, u64 b) {
    u64 d; asm("mul.rn.f32x2 %0, %1, %2;" : "=l"(d) : "l"(a), "l"(b)); return d;
}
__device__ __forceinline__ u64 add2(u64 a, u64 b) {
    u64 d; asm("add.rn.f32x2 %0, %1, %2;" : "=l"(d) : "l"(a), "l"(b)); return d;
}
__device__ __forceinline__ u64 abs2(u64 a) { return a & 0x7FFFFFFF7FFFFFFFULL; }

__global__ __launch_bounds__(128) void rk4_kernel(
    const float* __restrict__ x, const float* __restrict__ u,
    const float* __restrict__ W1, const float* __restrict__ b1,
    const float* __restrict__ W2, const float* __restrict__ b2,
    float* __restrict__ out, int B)
{
    int i = blockIdx.x * blockDim.x + threadIdx.x;
    int b0 = 2 * i;
    if (b0 >= B) return;

    // Per-pair inputs (coalesced float2 loads).
    float2 xv = reinterpret_cast<const float2*>(x)[i];
    float2 uv = reinterpret_cast<const float2*>(u)[i];

    // W1 is [2,4] row-major: row 0 multiplies s, row 1 multiplies u.
    // Fold u-contribution + b1 into per-thread packed bias c_j.
    u64 wa0, wa1, wa2, wa3, c0, c1, c2, c3, p0, p1, p2, p3, q0, q1, q2, q3;
    {
        float a0 = W1[0], a1 = W1[1], a2 = W1[2], a3 = W1[3];
        float u0 = W1[4], u1 = W1[5], u2 = W1[6], u3 = W1[7];
        wa0 = pack2(a0, a0); wa1 = pack2(a1, a1);
        wa2 = pack2(a2, a2); wa3 = pack2(a3, a3);
        c0 = pack2(fmaf(uv.x, u0, b1[0]), fmaf(uv.y, u0, b1[0]));
        c1 = pack2(fmaf(uv.x, u1, b1[1]), fmaf(uv.y, u1, b1[1]));
        c2 = pack2(fmaf(uv.x, u2, b1[2]), fmaf(uv.y, u2, b1[2]));
        c3 = pack2(fmaf(uv.x, u3, b1[3]), fmaf(uv.y, u3, b1[3]));
        float v0 = W2[0], v1 = W2[1], v2 = W2[2], v3 = W2[3];
        p0 = pack2(0.505f * v0, 0.505f * v0); q0 = pack2(0.495f * v0, 0.495f * v0);
        p1 = pack2(0.505f * v1, 0.505f * v1); q1 = pack2(0.495f * v1, 0.495f * v1);
        p2 = pack2(0.505f * v2, 0.505f * v2); q2 = pack2(0.495f * v2, 0.495f * v2);
        p3 = pack2(0.505f * v3, 0.505f * v3); q3 = pack2(0.495f * v3, 0.495f * v3);
    }
    const float bb2s = b2[0];
    const u64 bb    = pack2(bb2s, bb2s);
    const u64 half2 = pack2(0.5f, 0.5f);
    const u64 two2  = pack2(2.0f, 2.0f);
    const u64 six2  = pack2(0.16666667f, 0.16666667f);

    // dyn for two elements at once; lrelu folded into p/q coefficients.
    auto dyn = [&](u64 s2) -> u64 {
        u64 h0 = fma2(s2, wa0, c0);
        u64 h1 = fma2(s2, wa1, c1);
        u64 h2 = fma2(s2, wa2, c2);
        u64 h3 = fma2(s2, wa3, c3);
        u64 a = fma2(p0, h0, bb);
        a = fma2(q0, abs2(h0), a);
        a = fma2(p1, h1, a);
        a = fma2(q1, abs2(h1), a);
        u64 c = mul2(p2, h2);
        c = fma2(q2, abs2(h2), c);
        c = fma2(p3, h3, c);
        c = fma2(q3, abs2(h3), c);
        return add2(a, c);
    };

    auto stepf = [&](u64 s2) -> u64 {
        u64 k1 = dyn(s2);
        u64 k2 = dyn(fma2(half2, k1, s2));
        u64 k3 = dyn(fma2(half2, k2, s2));
        u64 k4 = dyn(add2(s2, k3));
        u64 t  = add2(k2, k3);
        u64 w  = add2(k1, k4);
        u64 sum = fma2(two2, t, w);
        return fma2(six2, sum, s2);
    };

    u64 s2 = pack2(xv.x, xv.y);

    float4* o0 = reinterpret_cast<float4*>(out + (size_t)b0 * NSTEPS);
    float4* o1 = reinterpret_cast<float4*>(out + (size_t)(b0 + 1) * NSTEPS);

    float4 v0, v1;
    // Group 0: t=0 is the initial state, then 3 steps.
    v0.x = xv.x; v1.x = xv.y;
    s2 = stepf(s2); unpack2(s2, v0.y, v1.y);
    s2 = stepf(s2); unpack2(s2, v0.z, v1.z);
    s2 = stepf(s2); unpack2(s2, v0.w, v1.w);
    o0[0] = v0; o1[0] = v1;

    // Remaining 24 groups of 4 steps (96 steps -> 99 total).
    // Keep loop body (~6KB SASS) un-unrolled to stay inside L0 I$.
    #pragma unroll 1
    for (int g = 1; g < NSTEPS / 4; ++g) {
        s2 = stepf(s2); unpack2(s2, v0.x, v1.x);
        s2 = stepf(s2); unpack2(s2, v0.y, v1.y);
        s2 = stepf(s2); unpack2(s2, v0.z, v1.z);
        s2 = stepf(s2); unpack2(s2, v0.w, v1.w);
        o0[g] = v0; o1[g] = v1;
    }
}

extern "C" void kernel_launch(void* const* d_in, const int* in_sizes, int n_in,
                              void* d_out, int out_size)
{
    const float* x  = (const float*)d_in[0];
    const float* u  = (const float*)d_in[1];
    const float* W1 = (const float*)d_in[2];
    const float* b1 = (const float*)d_in[3];
    const float* W2 = (const float*)d_in[4];
    const float* b2 = (const float*)d_in[5];
    float* out = (float*)d_out;
    int B = in_sizes[0];

    int nthreads = B / 2;                // 2 elements per thread
    int threads = 128;
    int blocks = (nthreads + threads - 1) / threads;
    rk4_kernel<<<blocks, threads>>>(x, u, W1, b1, W2, b2, out, B);
}

// round 5
// speedup vs baseline: 1.1812x; 1.0462x over previous
#include <cuda_runtime.h>

// Net_43490838839931: batched RK4 of ds/dt = MLP([s,u]) with 2->4->1 LeakyReLU net.
// R4: dyn fully refactored:
//   lrelu(h) = 0.505h + 0.495|h|  (slope 0.01)
//   sum_j w2_j*lrelu(h_j) + b2
//     = fma(P, s, Qt) + sum_j sign(w2_j)*|g_j|
//   where g_j = fma(q_j*w1a_j, s, q_j*c_j) = q_j*h_j  (|q_j| absorbed into g),
//         P = sum_j p_j*w1a_j (uniform), Qt = sum_j p_j*c_j + b2 (per thread),
//         p = 0.505*w2, q = 0.495*w2.
//   sign(w2_j)*|g_j| applied as one LOP3 per 32-bit half: (g & 0x7FFF..) | signbit.
// 2 elements/thread via packed f32x2; block=64 to smooth wave imbalance.

#define NSTEPS 100

typedef unsigned long long u64;

__device__ __forceinline__ u64 pack2(float lo, float hi) {
    u64 r; asm("mov.b64 %0, {%1, %2};" : "=l"(r) : "f"(lo), "f"(hi)); return r;
}
__device__ __forceinline__ void unpack2(u64 v, float& a, float& b) {
    asm("mov.b64 {%0, %1}, %2;" : "=f"(a), "=f"(b) : "l"(v));
}
__device__ __forceinline__ u64 fma2(u64 a, u64 b, u64 c) {
    u64 d; asm("fma.rn.f32x2 %0, %1, %2, %3;" : "=l"(d) : "l"(a), "l"(b), "l"(c)); return d;
}
__device__ __forceinline__ u64 add2(u64 a, u64 b) {
    u64 d; asm("add.rn.f32x2 %0, %1, %2;" : "=l"(d) : "l"(a), "l"(b)); return d;
}
// signed abs: (g & 0x7FFFFFFF) | sm  per half -> one LOP3 per 32-bit word
__device__ __forceinline__ u64 sabs2(u64 g, u64 sm) {
    return (g & 0x7FFFFFFF7FFFFFFFULL) | sm;
}

__global__ __launch_bounds__(64) void rk4_kernel(
    const float* __restrict__ x, const float* __restrict__ u,
    const float* __restrict__ W1, const float* __restrict__ b1,
    const float* __restrict__ W2, const float* __restrict__ b2,
    float* __restrict__ out, int B)
{
    int i = blockIdx.x * blockDim.x + threadIdx.x;
    int b0 = 2 * i;
    if (b0 >= B) return;

    float2 xv = reinterpret_cast<const float2*>(x)[i];
    float2 uv = reinterpret_cast<const float2*>(u)[i];

    // W1 [2,4] row-major: row 0 multiplies s, row 1 multiplies u.
    float a0 = W1[0], a1 = W1[1], a2 = W1[2], a3 = W1[3];
    float u0 = W1[4], u1 = W1[5], u2 = W1[6], u3 = W1[7];
    float v0 = W2[0], v1 = W2[1], v2 = W2[2], v3 = W2[3];

    float p0 = 0.505f * v0, p1 = 0.505f * v1, p2 = 0.505f * v2, p3 = 0.505f * v3;
    float q0 = 0.495f * v0, q1 = 0.495f * v1, q2 = 0.495f * v2, q3 = 0.495f * v3;

    // c_j per element: u*W1[1,j] + b1[j]
    float cx0 = fmaf(uv.x, u0, b1[0]), cy0 = fmaf(uv.y, u0, b1[0]);
    float cx1 = fmaf(uv.x, u1, b1[1]), cy1 = fmaf(uv.y, u1, b1[1]);
    float cx2 = fmaf(uv.x, u2, b1[2]), cy2 = fmaf(uv.y, u2, b1[2]);
    float cx3 = fmaf(uv.x, u3, b1[3]), cy3 = fmaf(uv.y, u3, b1[3]);

    // Linear part: P (uniform), Qt (per element)
    float Ps = fmaf(p0, a0, fmaf(p1, a1, fmaf(p2, a2, p3 * a3)));
    float bb = b2[0];
    float Qx = bb + fmaf(p0, cx0, fmaf(p1, cx1, fmaf(p2, cx2, p3 * cx3)));
    float Qy = bb + fmaf(p0, cy0, fmaf(p1, cy1, fmaf(p2, cy2, p3 * cy3)));

    const u64 P2  = pack2(Ps, Ps);
    const u64 Qt2 = pack2(Qx, Qy);

    // g_j = fma(R_j, s, D_j) with R_j = q_j*w1a_j (uniform), D_j = q_j*c_j.
    const u64 R0 = pack2(q0 * a0, q0 * a0);
    const u64 R1 = pack2(q1 * a1, q1 * a1);
    const u64 R2 = pack2(q2 * a2, q2 * a2);
    const u64 R3 = pack2(q3 * a3, q3 * a3);
    const u64 D0 = pack2(q0 * cx0, q0 * cy0);
    const u64 D1 = pack2(q1 * cx1, q1 * cy1);
    const u64 D2 = pack2(q2 * cx2, q2 * cy2);
    const u64 D3 = pack2(q3 * cx3, q3 * cy3);

    // sign masks: sm_j = 0x80000000_80000000 if w2_j < 0 else 0
    const u64 SM0 = (v0 < 0.0f) ? 0x8000000080000000ULL : 0ULL;
    const u64 SM1 = (v1 < 0.0f) ? 0x8000000080000000ULL : 0ULL;
    const u64 SM2 = (v2 < 0.0f) ? 0x8000000080000000ULL : 0ULL;
    const u64 SM3 = (v3 < 0.0f) ? 0x8000000080000000ULL : 0ULL;

    const u64 half2 = pack2(0.5f, 0.5f);
    const u64 two2  = pack2(2.0f, 2.0f);
    const u64 six2  = pack2(0.16666667f, 0.16666667f);

    // dyn: 5 fma2 + 8 LOP3 + 4 add2; chain depth ~21 cyc.
    auto dyn = [&](u64 s2) -> u64 {
        u64 g0 = fma2(s2, R0, D0);
        u64 g1 = fma2(s2, R1, D1);
        u64 g2 = fma2(s2, R2, D2);
        u64 g3 = fma2(s2, R3, D3);
        u64 lin = fma2(P2, s2, Qt2);
        u64 t01 = add2(sabs2(g0, SM0), sabs2(g1, SM1));
        u64 t23 = add2(sabs2(g2, SM2), sabs2(g3, SM3));
        u64 t   = add2(t01, t23);
        return add2(lin, t);
    };

    auto stepf = [&](u64 s2) -> u64 {
        u64 k1 = dyn(s2);
        u64 k2 = dyn(fma2(half2, k1, s2));
        u64 k3 = dyn(fma2(half2, k2, s2));
        u64 k4 = dyn(add2(s2, k3));
        u64 t  = add2(k2, k3);
        u64 w  = add2(k1, k4);
        u64 sum = fma2(two2, t, w);
        return fma2(six2, sum, s2);
    };

    u64 s2 = pack2(xv.x, xv.y);

    float4* o0 = reinterpret_cast<float4*>(out + (size_t)b0 * NSTEPS);
    float4* o1 = reinterpret_cast<float4*>(out + (size_t)(b0 + 1) * NSTEPS);

    float4 w0, w1;
    // Group 0: t=0 is the initial state, then 3 steps.
    w0.x = xv.x; w1.x = xv.y;
    s2 = stepf(s2); unpack2(s2, w0.y, w1.y);
    s2 = stepf(s2); unpack2(s2, w0.z, w1.z);
    s2 = stepf(s2); unpack2(s2, w0.w, w1.w);
    o0[0] = w0; o1[0] = w1;

    // Remaining 24 groups of 4 steps (96 steps -> 99 total).
    #pragma unroll 1
    for (int g = 1; g < NSTEPS / 4; ++g) {
        s2 = stepf(s2); unpack2(s2, w0.x, w1.x);
        s2 = stepf(s2); unpack2(s2, w0.y, w1.y);
        s2 = stepf(s2); unpack2(s2, w0.z, w1.z);
        s2 = stepf(s2); unpack2(s2, w0.w, w1.w);
        o0[g] = w0; o1[g] = w1;
    }
}

extern "C" void kernel_launch(void* const* d_in, const int* in_sizes, int n_in,
                              void* d_out, int out_size)
{
    const float* x  = (const float*)d_in[0];
    const float* u  = (const float*)d_in[1];
    const float* W1 = (const float*)d_in[2];
    const float* b1 = (const float*)d_in[3];
    const float* W2 = (const float*)d_in[4];
    const float* b2 = (const float*)d_in[5];
    float* out = (float*)d_out;
    int B = in_sizes[0];

    int nthreads = B / 2;                // 2 elements per thread
    int threads = 64;                    // small blocks -> smooth wave balance
    int blocks = (nthreads + threads - 1) / threads;
    rk4_kernel<<<blocks, threads>>>(x, u, W1, b1, W2, b2, out, B);
}

// round 6
// speedup vs baseline: 1.1822x; 1.0009x over previous
#include <cuda_runtime.h>

// Net_43490838839931: batched RK4 of ds/dt = MLP([s,u]) with 2->4->1 LeakyReLU net.
// R5: 4 elements/thread = TWO independent packed f32x2 chains interleaved for ILP.
//   dyn math (from R4):
//     dyn(s) = fma(P,s,Qt) + sum_j sign(w2_j)*|g_j|,  g_j = fma(q_j*w1a_j, s, q_j*c_j)
//     P, R_j uniform; Qt, D_j per element; sign applied via one LOP3 per word.

#define NSTEPS 100

typedef unsigned long long u64;

__device__ __forceinline__ u64 pack2(float lo, float hi) {
    u64 r; asm("mov.b64 %0, {%1, %2};" : "=l"(r) : "f"(lo), "f"(hi)); return r;
}
__device__ __forceinline__ void unpack2(u64 v, float& a, float& b) {
    asm("mov.b64 {%0, %1}, %2;" : "=f"(a), "=f"(b) : "l"(v));
}
__device__ __forceinline__ u64 fma2(u64 a, u64 b, u64 c) {
    u64 d; asm("fma.rn.f32x2 %0, %1, %2, %3;" : "=l"(d) : "l"(a), "l"(b), "l"(c)); return d;
}
__device__ __forceinline__ u64 add2(u64 a, u64 b) {
    u64 d; asm("add.rn.f32x2 %0, %1, %2;" : "=l"(d) : "l"(a), "l"(b)); return d;
}
__device__ __forceinline__ u64 sabs2(u64 g, u64 sm) {
    return (g & 0x7FFFFFFF7FFFFFFFULL) | sm;  // one LOP3 per 32-bit half
}

struct Chain {          // per-pair state (2 elements packed)
    u64 Qt, D0, D1, D2, D3, s;
};

__global__ __launch_bounds__(64) void rk4_kernel(
    const float* __restrict__ x, const float* __restrict__ u,
    const float* __restrict__ W1, const float* __restrict__ b1,
    const float* __restrict__ W2, const float* __restrict__ b2,
    float* __restrict__ out, int B)
{
    int i = blockIdx.x * blockDim.x + threadIdx.x;
    int b0 = 4 * i;
    if (b0 >= B) return;

    float4 xv = reinterpret_cast<const float4*>(x)[i];
    float4 uv = reinterpret_cast<const float4*>(u)[i];

    // W1 [2,4] row-major: row 0 multiplies s, row 1 multiplies u.
    float a0 = W1[0], a1 = W1[1], a2 = W1[2], a3 = W1[3];
    float u0 = W1[4], u1 = W1[5], u2 = W1[6], u3 = W1[7];
    float v0 = W2[0], v1 = W2[1], v2 = W2[2], v3 = W2[3];

    float p0 = 0.505f * v0, p1 = 0.505f * v1, p2 = 0.505f * v2, p3 = 0.505f * v3;
    float q0 = 0.495f * v0, q1 = 0.495f * v1, q2 = 0.495f * v2, q3 = 0.495f * v3;
    float bb = b2[0];
    float Ps = fmaf(p0, a0, fmaf(p1, a1, fmaf(p2, a2, p3 * a3)));

    // Uniform packed constants.
    const u64 P2 = pack2(Ps, Ps);
    const u64 R0 = pack2(q0 * a0, q0 * a0);
    const u64 R1 = pack2(q1 * a1, q1 * a1);
    const u64 R2 = pack2(q2 * a2, q2 * a2);
    const u64 R3 = pack2(q3 * a3, q3 * a3);
    const u64 SM0 = (v0 < 0.0f) ? 0x8000000080000000ULL : 0ULL;
    const u64 SM1 = (v1 < 0.0f) ? 0x8000000080000000ULL : 0ULL;
    const u64 SM2 = (v2 < 0.0f) ? 0x8000000080000000ULL : 0ULL;
    const u64 SM3 = (v3 < 0.0f) ? 0x8000000080000000ULL : 0ULL;
    const u64 half2 = pack2(0.5f, 0.5f);
    const u64 two2  = pack2(2.0f, 2.0f);
    const u64 six2  = pack2(0.16666667f, 0.16666667f);

    // Build per-pair state.
    auto mkchain = [&](float xe, float xo, float ue, float uo) -> Chain {
        Chain ch;
        float ce0 = fmaf(ue, u0, b1[0]), co0 = fmaf(uo, u0, b1[0]);
        float ce1 = fmaf(ue, u1, b1[1]), co1 = fmaf(uo, u1, b1[1]);
        float ce2 = fmaf(ue, u2, b1[2]), co2 = fmaf(uo, u2, b1[2]);
        float ce3 = fmaf(ue, u3, b1[3]), co3 = fmaf(uo, u3, b1[3]);
        float Qe = bb + fmaf(p0, ce0, fmaf(p1, ce1, fmaf(p2, ce2, p3 * ce3)));
        float Qo = bb + fmaf(p0, co0, fmaf(p1, co1, fmaf(p2, co2, p3 * co3)));
        ch.Qt = pack2(Qe, Qo);
        ch.D0 = pack2(q0 * ce0, q0 * co0);
        ch.D1 = pack2(q1 * ce1, q1 * co1);
        ch.D2 = pack2(q2 * ce2, q2 * co2);
        ch.D3 = pack2(q3 * ce3, q3 * co3);
        ch.s  = pack2(xe, xo);
        return ch;
    };

    Chain A = mkchain(xv.x, xv.y, uv.x, uv.y);
    Chain Bc = mkchain(xv.z, xv.w, uv.z, uv.w);

    auto dyn = [&](const Chain& ch, u64 s2) -> u64 {
        u64 g0 = fma2(s2, R0, ch.D0);
        u64 g1 = fma2(s2, R1, ch.D1);
        u64 g2 = fma2(s2, R2, ch.D2);
        u64 g3 = fma2(s2, R3, ch.D3);
        u64 lin = fma2(P2, s2, ch.Qt);
        u64 t01 = add2(sabs2(g0, SM0), sabs2(g1, SM1));
        u64 t23 = add2(sabs2(g2, SM2), sabs2(g3, SM3));
        return add2(lin, add2(t01, t23));
    };

    // One RK4 step for BOTH chains, interleaved for ILP.
    auto step2 = [&]() {
        u64 k1a = dyn(A, A.s);
        u64 k1b = dyn(Bc, Bc.s);
        u64 k2a = dyn(A, fma2(half2, k1a, A.s));
        u64 k2b = dyn(Bc, fma2(half2, k1b, Bc.s));
        u64 k3a = dyn(A, fma2(half2, k2a, A.s));
        u64 k3b = dyn(Bc, fma2(half2, k2b, Bc.s));
        u64 k4a = dyn(A, add2(A.s, k3a));
        u64 k4b = dyn(Bc, add2(Bc.s, k3b));
        u64 suma = fma2(two2, add2(k2a, k3a), add2(k1a, k4a));
        u64 sumb = fma2(two2, add2(k2b, k3b), add2(k1b, k4b));
        A.s  = fma2(six2, suma, A.s);
        Bc.s = fma2(six2, sumb, Bc.s);
    };

    float4* o0 = reinterpret_cast<float4*>(out + (size_t)b0 * NSTEPS);
    float4* o1 = reinterpret_cast<float4*>(out + (size_t)(b0 + 1) * NSTEPS);
    float4* o2 = reinterpret_cast<float4*>(out + (size_t)(b0 + 2) * NSTEPS);
    float4* o3 = reinterpret_cast<float4*>(out + (size_t)(b0 + 3) * NSTEPS);

    float4 w0, w1, w2, w3;
    // Group 0: t=0 is the initial state, then 3 steps.
    w0.x = xv.x; w1.x = xv.y; w2.x = xv.z; w3.x = xv.w;
    step2(); unpack2(A.s, w0.y, w1.y); unpack2(Bc.s, w2.y, w3.y);
    step2(); unpack2(A.s, w0.z, w1.z); unpack2(Bc.s, w2.z, w3.z);
    step2(); unpack2(A.s, w0.w, w1.w); unpack2(Bc.s, w2.w, w3.w);
    o0[0] = w0; o1[0] = w1; o2[0] = w2; o3[0] = w3;

    // Remaining 24 groups of 4 steps (96 steps -> 99 total).
    #pragma unroll 1
    for (int g = 1; g < NSTEPS / 4; ++g) {
        step2(); unpack2(A.s, w0.x, w1.x); unpack2(Bc.s, w2.x, w3.x);
        step2(); unpack2(A.s, w0.y, w1.y); unpack2(Bc.s, w2.y, w3.y);
        step2(); unpack2(A.s, w0.z, w1.z); unpack2(Bc.s, w2.z, w3.z);
        step2(); unpack2(A.s, w0.w, w1.w); unpack2(Bc.s, w2.w, w3.w);
        o0[g] = w0; o1[g] = w1; o2[g] = w2; o3[g] = w3;
    }
}

extern "C" void kernel_launch(void* const* d_in, const int* in_sizes, int n_in,
                              void* d_out, int out_size)
{
    const float* x  = (const float*)d_in[0];
    const float* u  = (const float*)d_in[1];
    const float* W1 = (const float*)d_in[2];
    const float* b1 = (const float*)d_in[3];
    const float* W2 = (const float*)d_in[4];
    const float* b2 = (const float*)d_in[5];
    float* out = (float*)d_out;
    int B = in_sizes[0];

    int nthreads = B / 4;                // 4 elements per thread (2 packed chains)
    int threads = 64;
    int blocks = (nthreads + threads - 1) / threads;
    rk4_kernel<<<blocks, threads>>>(x, u, W1, b1, W2, b2, out, B);
}

// round 10
// speedup vs baseline: 1.2267x; 1.0376x over previous
#include <cuda_runtime.h>

// Net_43490838839931: batched RK4 of ds/dt = MLP([s,u]) with 2->4->1 LeakyReLU net.
// R6: incremental RK4 stages. Since hinge args are affine in s:
//   g_j(s)        = R_j*s + D_j           (stage 1, also keeps lin1 = P*s+Qt)
//   g_j(s+0.5k)   = fma(k, 0.5R_j, g_j0)  (stages 2,3 — no explicit stage arg)
//   g_j(s+k3)     = fma(k3, R_j,  g_j0)   (stage 4)
// 40 fma-pipe lane-ops/element-step (was 43). Two independent packed chains/thread.
//   dyn(s) = lin + sum_j sign(w2_j)*|g_j|, sign applied via one LOP3 per word.

#define NSTEPS 100

typedef unsigned long long u64;

__device__ __forceinline__ u64 pack2(float lo, float hi) {
    u64 r; asm("mov.b64 %0, {%1, %2};" : "=l"(r) : "f"(lo), "f"(hi)); return r;
}
__device__ __forceinline__ void unpack2(u64 v, float& a, float& b) {
    asm("mov.b64 {%0, %1}, %2;" : "=f"(a), "=f"(b) : "l"(v));
}
__device__ __forceinline__ u64 fma2(u64 a, u64 b, u64 c) {
    u64 d; asm("fma.rn.f32x2 %0, %1, %2, %3;" : "=l"(d) : "l"(a), "l"(b), "l"(c)); return d;
}
__device__ __forceinline__ u64 add2(u64 a, u64 b) {
    u64 d; asm("add.rn.f32x2 %0, %1, %2;" : "=l"(d) : "l"(a), "l"(b)); return d;
}
__device__ __forceinline__ u64 sabs2(u64 g, u64 sm) {
    return (g & 0x7FFFFFFF7FFFFFFFULL) | sm;  // one LOP3 per 32-bit half
}

struct Chain {          // per-pair state (2 elements packed)
    u64 Qt, D0, D1, D2, D3, s;
};

__global__ __launch_bounds__(64) void rk4_kernel(
    const float* __restrict__ x, const float* __restrict__ u,
    const float* __restrict__ W1, const float* __restrict__ b1,
    const float* __restrict__ W2, const float* __restrict__ b2,
    float* __restrict__ out, int B)
{
    int i = blockIdx.x * blockDim.x + threadIdx.x;
    int b0 = 4 * i;
    if (b0 >= B) return;

    float4 xv = reinterpret_cast<const float4*>(x)[i];
    float4 uv = reinterpret_cast<const float4*>(u)[i];

    // W1 [2,4] row-major: row 0 multiplies s, row 1 multiplies u.
    float a0 = W1[0], a1 = W1[1], a2 = W1[2], a3 = W1[3];
    float u0 = W1[4], u1 = W1[5], u2 = W1[6], u3 = W1[7];
    float v0 = W2[0], v1 = W2[1], v2 = W2[2], v3 = W2[3];

    float p0 = 0.505f * v0, p1 = 0.505f * v1, p2 = 0.505f * v2, p3 = 0.505f * v3;
    float q0 = 0.495f * v0, q1 = 0.495f * v1, q2 = 0.495f * v2, q3 = 0.495f * v3;
    float bb = b2[0];
    float Ps = fmaf(p0, a0, fmaf(p1, a1, fmaf(p2, a2, p3 * a3)));

    float r0 = q0 * a0, r1 = q1 * a1, r2 = q2 * a2, r3 = q3 * a3;

    // Uniform packed constants (full and half versions for incremental stages).
    const u64 P2  = pack2(Ps, Ps);
    const u64 hP2 = pack2(0.5f * Ps, 0.5f * Ps);
    const u64 R0 = pack2(r0, r0),            R1 = pack2(r1, r1);
    const u64 R2 = pack2(r2, r2),            R3 = pack2(r3, r3);
    const u64 hR0 = pack2(0.5f * r0, 0.5f * r0), hR1 = pack2(0.5f * r1, 0.5f * r1);
    const u64 hR2 = pack2(0.5f * r2, 0.5f * r2), hR3 = pack2(0.5f * r3, 0.5f * r3);
    const u64 SM0 = (v0 < 0.0f) ? 0x8000000080000000ULL : 0ULL;
    const u64 SM1 = (v1 < 0.0f) ? 0x8000000080000000ULL : 0ULL;
    const u64 SM2 = (v2 < 0.0f) ? 0x8000000080000000ULL : 0ULL;
    const u64 SM3 = (v3 < 0.0f) ? 0x8000000080000000ULL : 0ULL;
    const u64 two2 = pack2(2.0f, 2.0f);
    const u64 six2 = pack2(0.16666667f, 0.16666667f);

    auto mkchain = [&](float xe, float xo, float ue, float uo) -> Chain {
        Chain ch;
        float ce0 = fmaf(ue, u0, b1[0]), co0 = fmaf(uo, u0, b1[0]);
        float ce1 = fmaf(ue, u1, b1[1]), co1 = fmaf(uo, u1, b1[1]);
        float ce2 = fmaf(ue, u2, b1[2]), co2 = fmaf(uo, u2, b1[2]);
        float ce3 = fmaf(ue, u3, b1[3]), co3 = fmaf(uo, u3, b1[3]);
        float Qe = bb + fmaf(p0, ce0, fmaf(p1, ce1, fmaf(p2, ce2, p3 * ce3)));
        float Qo = bb + fmaf(p0, co0, fmaf(p1, co1, fmaf(p2, co2, p3 * co3)));
        ch.Qt = pack2(Qe, Qo);
        ch.D0 = pack2(q0 * ce0, q0 * co0);
        ch.D1 = pack2(q1 * ce1, q1 * co1);
        ch.D2 = pack2(q2 * ce2, q2 * co2);
        ch.D3 = pack2(q3 * ce3, q3 * co3);
        ch.s  = pack2(xe, xo);
        return ch;
    };

    Chain A = mkchain(xv.x, xv.y, uv.x, uv.y);
    Chain Bc = mkchain(xv.z, xv.w, uv.z, uv.w);

    // abs-sum tree + lin: 4 add2 (+8 LOP3 on alu pipe)
    auto combine = [&](u64 g0, u64 g1, u64 g2, u64 g3, u64 lin) -> u64 {
        u64 t01 = add2(sabs2(g0, SM0), sabs2(g1, SM1));
        u64 t23 = add2(sabs2(g2, SM2), sabs2(g3, SM3));
        return add2(lin, add2(t01, t23));
    };

    // One RK4 step for one chain: 40 fma-pipe wide-ops total with stage-arg folding.
    auto step1 = [&](Chain& ch) {
        // stage 1 at s
        u64 g0 = fma2(ch.s, R0, ch.D0);
        u64 g1 = fma2(ch.s, R1, ch.D1);
        u64 g2 = fma2(ch.s, R2, ch.D2);
        u64 g3 = fma2(ch.s, R3, ch.D3);
        u64 lin1 = fma2(P2, ch.s, ch.Qt);
        u64 k1 = combine(g0, g1, g2, g3, lin1);
        // stage 2 at s + 0.5*k1 (incremental)
        u64 h0 = fma2(k1, hR0, g0);
        u64 h1 = fma2(k1, hR1, g1);
        u64 h2 = fma2(k1, hR2, g2);
        u64 h3 = fma2(k1, hR3, g3);
        u64 lin2 = fma2(k1, hP2, lin1);
        u64 k2 = combine(h0, h1, h2, h3, lin2);
        // stage 3 at s + 0.5*k2
        u64 m0 = fma2(k2, hR0, g0);
        u64 m1 = fma2(k2, hR1, g1);
        u64 m2 = fma2(k2, hR2, g2);
        u64 m3 = fma2(k2, hR3, g3);
        u64 lin3 = fma2(k2, hP2, lin1);
        u64 k3 = combine(m0, m1, m2, m3, lin3);
        // stage 4 at s + k3
        u64 n0 = fma2(k3, R0, g0);
        u64 n1 = fma2(k3, R1, g1);
        u64 n2 = fma2(k3, R2, g2);
        u64 n3 = fma2(k3, R3, g3);
        u64 lin4 = fma2(k3, P2, lin1);
        u64 k4 = combine(n0, n1, n2, n3, lin4);
        // combine
        u64 t = add2(k2, k3);
        u64 w = add2(k1, k4);
        u64 sum = fma2(two2, t, w);
        ch.s = fma2(six2, sum, ch.s);
    };

    auto step2 = [&]() { step1(A); step1(Bc); };

    float4* o0 = reinterpret_cast<float4*>(out + (size_t)b0 * NSTEPS);
    float4* o1 = reinterpret_cast<float4*>(out + (size_t)(b0 + 1) * NSTEPS);
    float4* o2 = reinterpret_cast<float4*>(out + (size_t)(b0 + 2) * NSTEPS);
    float4* o3 = reinterpret_cast<float4*>(out + (size_t)(b0 + 3) * NSTEPS);

    float4 w0, w1, w2, w3;
    // Group 0: t=0 is the initial state, then 3 steps.
    w0.x = xv.x; w1.x = xv.y; w2.x = xv.z; w3.x = xv.w;
    step2(); unpack2(A.s, w0.y, w1.y); unpack2(Bc.s, w2.y, w3.y);
    step2(); unpack2(A.s, w0.z, w1.z); unpack2(Bc.s, w2.z, w3.z);
    step2(); unpack2(A.s, w0.w, w1.w); unpack2(Bc.s, w2.w, w3.w);
    o0[0] = w0; o1[0] = w1; o2[0] = w2; o3[0] = w3;

    // Remaining 24 groups of 4 steps (96 steps -> 99 total).
    #pragma unroll 1
    for (int g = 1; g < NSTEPS / 4; ++g) {
        step2(); unpack2(A.s, w0.x, w1.x); unpack2(Bc.s, w2.x, w3.x);
        step2(); unpack2(A.s, w0.y, w1.y); unpack2(Bc.s, w2.y, w3.y);
        step2(); unpack2(A.s, w0.z, w1.z); unpack2(Bc.s, w2.z, w3.z);
        step2(); unpack2(A.s, w0.w, w1.w); unpack2(Bc.s, w2.w, w3.w);
        o0[g] = w0; o1[g] = w1; o2[g] = w2; o3[g] = w3;
    }
}

extern "C" void kernel_launch(void* const* d_in, const int* in_sizes, int n_in,
                              void* d_out, int out_size)
{
    const float* x  = (const float*)d_in[0];
    const float* u  = (const float*)d_in[1];
    const float* W1 = (const float*)d_in[2];
    const float* b1 = (const float*)d_in[3];
    const float* W2 = (const float*)d_in[4];
    const float* b2 = (const float*)d_in[5];
    float* out = (float*)d_out;
    int B = in_sizes[0];

    int nthreads = B / 4;                // 4 elements per thread (2 packed chains)
    int threads = 64;
    int blocks = (nthreads + threads - 1) / threads;
    rk4_kernel<<<blocks, threads>>>(x, u, W1, b1, W2, b2, out, B);
}

// round 13
// speedup vs baseline: 1.5323x; 1.2491x over previous
#include <cuda_runtime.h>
#include <math.h>

// Net_43490838839931: batched RK4 of ds/dt = MLP([s,u]) with 2->4->1 LeakyReLU net.
// R7: scalar math, sign-specialized (16-way) so sign*|g| folds into FADD ±|src|
// operand modifiers (zero-cost in SASS). Incremental RK4 stages as R6:
//   g_j(s) = R_j*s + D_j ; stage2/3: fma(k, 0.5R_j, g_j) ; stage4: fma(k3, R_j, g_j)
//   dyn = lin + sum_j sign(w2_j)*|g_j|
// 4 elements/thread = 4 independent scalar chains (ILP). block=32, 1024 blocks.

#define NSTEPS 100

struct Uni {
    float R0, R1, R2, R3;      // q_j * w1a_j
    float hR0, hR1, hR2, hR3;  // 0.5 * R_j
    float P, hP;               // sum p_j*w1a_j, half of it
};

struct El {                    // per-element state
    float Qt, D0, D1, D2, D3, s;
};

template <int SGN>
__device__ __forceinline__ float dynsum(float g0, float g1, float g2, float g3,
                                        float lin) {
    // FADD with ±|src| modifiers — abs and sign are free in SASS.
    float A0 = (SGN & 1) ? -fabsf(g0) : fabsf(g0);
    float A1 = (SGN & 2) ? -fabsf(g1) : fabsf(g1);
    float A2 = (SGN & 4) ? -fabsf(g2) : fabsf(g2);
    float A3 = (SGN & 8) ? -fabsf(g3) : fabsf(g3);
    return lin + ((A0 + A1) + (A2 + A3));
}

template <int SGN>
__device__ __forceinline__ void step1(const Uni& U, El& e) {
    // stage 1 at s
    float g0 = fmaf(e.s, U.R0, e.D0);
    float g1 = fmaf(e.s, U.R1, e.D1);
    float g2 = fmaf(e.s, U.R2, e.D2);
    float g3 = fmaf(e.s, U.R3, e.D3);
    float lin1 = fmaf(U.P, e.s, e.Qt);
    float k1 = dynsum<SGN>(g0, g1, g2, g3, lin1);
    // stage 2 at s + 0.5*k1 (incremental)
    float h0 = fmaf(k1, U.hR0, g0);
    float h1 = fmaf(k1, U.hR1, g1);
    float h2 = fmaf(k1, U.hR2, g2);
    float h3 = fmaf(k1, U.hR3, g3);
    float lin2 = fmaf(k1, U.hP, lin1);
    float k2 = dynsum<SGN>(h0, h1, h2, h3, lin2);
    // stage 3 at s + 0.5*k2
    float m0 = fmaf(k2, U.hR0, g0);
    float m1 = fmaf(k2, U.hR1, g1);
    float m2 = fmaf(k2, U.hR2, g2);
    float m3 = fmaf(k2, U.hR3, g3);
    float lin3 = fmaf(k2, U.hP, lin1);
    float k3 = dynsum<SGN>(m0, m1, m2, m3, lin3);
    // stage 4 at s + k3
    float n0 = fmaf(k3, U.R0, g0);
    float n1 = fmaf(k3, U.R1, g1);
    float n2 = fmaf(k3, U.R2, g2);
    float n3 = fmaf(k3, U.R3, g3);
    float lin4 = fmaf(k3, U.P, lin1);
    float k4 = dynsum<SGN>(n0, n1, n2, n3, lin4);
    // combine
    float t = k2 + k3;
    float w = k1 + k4;
    float sum = fmaf(2.0f, t, w);
    e.s = fmaf(sum, 0.16666667f, e.s);
}

template <int SGN>
__device__ __forceinline__ void run_loop(const Uni& U, El (&E)[4], float4 xv,
                                         float4* o0, float4* o1, float4* o2,
                                         float4* o3) {
    float4 w0, w1, w2, w3;
    // Group 0: t=0 is the initial state, then 3 steps.
    w0.x = xv.x; w1.x = xv.y; w2.x = xv.z; w3.x = xv.w;
    #pragma unroll
    for (int e = 0; e < 4; ++e) step1<SGN>(U, E[e]);
    w0.y = E[0].s; w1.y = E[1].s; w2.y = E[2].s; w3.y = E[3].s;
    #pragma unroll
    for (int e = 0; e < 4; ++e) step1<SGN>(U, E[e]);
    w0.z = E[0].s; w1.z = E[1].s; w2.z = E[2].s; w3.z = E[3].s;
    #pragma unroll
    for (int e = 0; e < 4; ++e) step1<SGN>(U, E[e]);
    w0.w = E[0].s; w1.w = E[1].s; w2.w = E[2].s; w3.w = E[3].s;
    o0[0] = w0; o1[0] = w1; o2[0] = w2; o3[0] = w3;

    // Remaining 24 groups of 4 steps (96 steps -> 99 total).
    #pragma unroll 1
    for (int g = 1; g < NSTEPS / 4; ++g) {
        #pragma unroll
        for (int e = 0; e < 4; ++e) step1<SGN>(U, E[e]);
        w0.x = E[0].s; w1.x = E[1].s; w2.x = E[2].s; w3.x = E[3].s;
        #pragma unroll
        for (int e = 0; e < 4; ++e) step1<SGN>(U, E[e]);
        w0.y = E[0].s; w1.y = E[1].s; w2.y = E[2].s; w3.y = E[3].s;
        #pragma unroll
        for (int e = 0; e < 4; ++e) step1<SGN>(U, E[e]);
        w0.z = E[0].s; w1.z = E[1].s; w2.z = E[2].s; w3.z = E[3].s;
        #pragma unroll
        for (int e = 0; e < 4; ++e) step1<SGN>(U, E[e]);
        w0.w = E[0].s; w1.w = E[1].s; w2.w = E[2].s; w3.w = E[3].s;
        o0[g] = w0; o1[g] = w1; o2[g] = w2; o3[g] = w3;
    }
}

__global__ __launch_bounds__(32) void rk4_kernel(
    const float* __restrict__ x, const float* __restrict__ u,
    const float* __restrict__ W1, const float* __restrict__ b1,
    const float* __restrict__ W2, const float* __restrict__ b2,
    float* __restrict__ out, int B)
{
    int i = blockIdx.x * blockDim.x + threadIdx.x;
    int b0 = 4 * i;
    if (b0 >= B) return;

    float4 xv = reinterpret_cast<const float4*>(x)[i];
    float4 uv = reinterpret_cast<const float4*>(u)[i];

    // W1 [2,4] row-major: row 0 multiplies s, row 1 multiplies u.
    float a0 = W1[0], a1 = W1[1], a2 = W1[2], a3 = W1[3];
    float u0 = W1[4], u1 = W1[5], u2 = W1[6], u3 = W1[7];
    float v0 = W2[0], v1 = W2[1], v2 = W2[2], v3 = W2[3];

    float p0 = 0.505f * v0, p1 = 0.505f * v1, p2 = 0.505f * v2, p3 = 0.505f * v3;
    float q0 = 0.495f * v0, q1 = 0.495f * v1, q2 = 0.495f * v2, q3 = 0.495f * v3;
    float bb = b2[0];

    Uni U;
    U.R0 = q0 * a0; U.R1 = q1 * a1; U.R2 = q2 * a2; U.R3 = q3 * a3;
    U.hR0 = 0.5f * U.R0; U.hR1 = 0.5f * U.R1;
    U.hR2 = 0.5f * U.R2; U.hR3 = 0.5f * U.R3;
    U.P = fmaf(p0, a0, fmaf(p1, a1, fmaf(p2, a2, p3 * a3)));
    U.hP = 0.5f * U.P;

    const float us[4] = {uv.x, uv.y, uv.z, uv.w};
    const float xs[4] = {xv.x, xv.y, xv.z, xv.w};
    El E[4];
    #pragma unroll
    for (int e = 0; e < 4; ++e) {
        float c0 = fmaf(us[e], u0, b1[0]);
        float c1 = fmaf(us[e], u1, b1[1]);
        float c2 = fmaf(us[e], u2, b1[2]);
        float c3 = fmaf(us[e], u3, b1[3]);
        E[e].Qt = bb + fmaf(p0, c0, fmaf(p1, c1, fmaf(p2, c2, p3 * c3)));
        E[e].D0 = q0 * c0; E[e].D1 = q1 * c1;
        E[e].D2 = q2 * c2; E[e].D3 = q3 * c3;
        E[e].s = xs[e];
    }

    float4* o0 = reinterpret_cast<float4*>(out + (size_t)b0 * NSTEPS);
    float4* o1 = reinterpret_cast<float4*>(out + (size_t)(b0 + 1) * NSTEPS);
    float4* o2 = reinterpret_cast<float4*>(out + (size_t)(b0 + 2) * NSTEPS);
    float4* o3 = reinterpret_cast<float4*>(out + (size_t)(b0 + 3) * NSTEPS);

    // 4-bit sign code of W2 (uniform across all threads -> no divergence).
    int code = (v0 < 0.0f ? 1 : 0) | (v1 < 0.0f ? 2 : 0) |
               (v2 < 0.0f ? 4 : 0) | (v3 < 0.0f ? 8 : 0);

    switch (code) {
        case 0:  run_loop<0 >(U, E, xv, o0, o1, o2, o3); break;
        case 1:  run_loop<1 >(U, E, xv, o0, o1, o2, o3); break;
        case 2:  run_loop<2 >(U, E, xv, o0, o1, o2, o3); break;
        case 3:  run_loop<3 >(U, E, xv, o0, o1, o2, o3); break;
        case 4:  run_loop<4 >(U, E, xv, o0, o1, o2, o3); break;
        case 5:  run_loop<5 >(U, E, xv, o0, o1, o2, o3); break;
        case 6:  run_loop<6 >(U, E, xv, o0, o1, o2, o3); break;
        case 7:  run_loop<7 >(U, E, xv, o0, o1, o2, o3); break;
        case 8:  run_loop<8 >(U, E, xv, o0, o1, o2, o3); break;
        case 9:  run_loop<9 >(U, E, xv, o0, o1, o2, o3); break;
        case 10: run_loop<10>(U, E, xv, o0, o1, o2, o3); break;
        case 11: run_loop<11>(U, E, xv, o0, o1, o2, o3); break;
        case 12: run_loop<12>(U, E, xv, o0, o1, o2, o3); break;
        case 13: run_loop<13>(U, E, xv, o0, o1, o2, o3); break;
        case 14: run_loop<14>(U, E, xv, o0, o1, o2, o3); break;
        case 15: run_loop<15>(U, E, xv, o0, o1, o2, o3); break;
    }
}

extern "C" void kernel_launch(void* const* d_in, const int* in_sizes, int n_in,
                              void* d_out, int out_size)
{
    const float* x  = (const float*)d_in[0];
    const float* u  = (const float*)d_in[1];
    const float* W1 = (const float*)d_in[2];
    const float* b1 = (const float*)d_in[3];
    const float* W2 = (const float*)d_in[4];
    const float* b2 = (const float*)d_in[5];
    float* out = (float*)d_out;
    int B = in_sizes[0];

    int nthreads = B / 4;                // 4 elements per thread (4 scalar chains)
    int threads = 32;                    // 1 warp/block; 1024 blocks -> 6.9/SM
    int blocks = (nthreads + threads - 1) / threads;
    rk4_kernel<<<blocks, threads>>>(x, u, W1, b1, W2, b2, out, B);
}